// round 14
// baseline (speedup 1.0000x reference)
#include <cuda_runtime.h>
#include <cuda_bf16.h>
#include <cstdint>
#include <math.h>

#define NS 65536
typedef uint32_t u32;
typedef uint64_t u64;

// ===== arch-specific feature gate (tcgen05 only exists on sm_103a pass) ====
#if defined(__CUDA_ARCH__) && (defined(__CUDA_ARCH_FEAT_SM103_ALL) || \
    (defined(__CUDA_ARCH_SPECIFIC__) && (__CUDA_ARCH_SPECIFIC__ == 1030)) || \
    (defined(__CUDA_ARCH_FAMILY_SPECIFIC__) && (__CUDA_ARCH_FAMILY_SPECIFIC__ == 1030)))
#define HAS_TC 1
#else
#define HAS_TC 0
#endif

// ======================= global scratch (no runtime alloc) =================
__device__ __align__(256) unsigned char g_wscr[6u * 256u * 1024u];
__device__ float g_b0p[512], g_wih0p[512], g_b1p[512];
__device__ float g_c0[128u * NS];
__device__ float g_c1[128u * NS];
__device__ float g_hs[128u * NS];
__device__ int   g_use_tc;

__host__ __device__ __forceinline__ u32 swz(u32 b) { return b ^ ((b >> 3) & 0x70); }

// ======================= smem map (bytes) ==================================
#define OFF_TMEM   0
#define OFF_B0P    64
#define OFF_WIH    2112
#define OFF_B1P    4160
#define OFF_BD     6208
#define OFF_WO     9280
#define OFF_BO     13376
#define OFF_MB     13440      // full0..3 (+0..31), empty0..3 (+32..63), gdA(+64), gdB(+72), epL(+80), epH(+88)
#define OFF_BBUF   16384      // 4 x 16KB
#define OFF_AREG   81920      // 128KB
#define SMEM_BYTES 212992
#define A_H1HI (OFF_AREG)
#define A_H0HI (OFF_AREG + 32768)
#define A_H1LO (OFF_AREG + 65536)
#define A_H0LO (OFF_AREG + 98304)

#define SLAB 16384u
#define IDESC128 0x8200490u   // f32 accum, bf16xbf16, M=128, N=128
static __device__ __forceinline__ u64 mkdesc(u32 smem_addr) {
    return (u64(2) << 61) | (u64(1) << 46) | (u64(64) << 32) | (u64(1) << 16)
         | ((u64)(smem_addr >> 4) & 0x3FFF);
}

// ======================= PTX helpers =======================================
__device__ __forceinline__ u32 smem_u32(const void* p) {
    u32 a; asm("{ .reg .u64 t; cvta.to.shared.u64 t, %1; cvt.u32.u64 %0, t; }" : "=r"(a) : "l"(p));
    return a;
}
#define MBAR_INIT(a, c) asm volatile("mbarrier.init.shared.b64 [%0], %1;" :: "r"(a), "r"(c) : "memory")
#define MBAR_EXPECT(a, b) asm volatile("mbarrier.arrive.expect_tx.shared.b64 _, [%0], %1;" :: "r"(a), "r"(b) : "memory")
#define MBAR_ARRIVE(a) asm volatile("mbarrier.arrive.release.cta.shared::cta.b64 _, [%0];" :: "r"(a) : "memory")
#define MBAR_WAIT(a, ph) do { \
    asm volatile("{\n\t.reg .pred P;\n\tWL%=:\n\t" \
        "mbarrier.try_wait.parity.acquire.cta.shared::cta.b64 P, [%0], %1, 0x989680;\n\t" \
        "@P bra.uni WD%=;\n\tbra.uni WL%=;\n\tWD%=:\n\t}" \
        :: "r"(a), "r"(ph) : "memory"); } while (0)
#define BULKCP(dst, src, mbar) asm volatile( \
    "cp.async.bulk.shared::cluster.global.mbarrier::complete_tx::bytes [%0], [%1], %2, [%3];" \
    :: "r"(dst), "l"(src), "r"(SLAB), "r"(mbar) : "memory")
#define FENCE_ASYNC() asm volatile("fence.proxy.async.shared::cta;" ::: "memory")

#if HAS_TC
#define T5_COMMIT(a) asm volatile( \
    "tcgen05.commit.cta_group::1.mbarrier::arrive::one.shared::cluster.b64 [%0];" :: "r"(a) : "memory")
#define T5_ALLOC(a, n) asm volatile( \
    "tcgen05.alloc.cta_group::1.sync.aligned.shared::cta.b32 [%0], %1;" :: "r"(a), "r"(n) : "memory")
#define T5_DEALLOC(t, n) asm volatile( \
    "tcgen05.dealloc.cta_group::1.sync.aligned.b32 %0, %1;" :: "r"(t), "r"(n))
#define T5_WAIT_LD() asm volatile("tcgen05.wait::ld.sync.aligned;" ::: "memory")
#define T5_FENCE_B() asm volatile("tcgen05.fence::before_thread_sync;" ::: "memory")
#define T5_FENCE_A() asm volatile("tcgen05.fence::after_thread_sync;" ::: "memory")
__device__ __forceinline__ void mma_ss(u32 d, u64 ad, u64 bd_, u32 en) {
    asm volatile(
        "{\n\t.reg .pred p;\n\tsetp.ne.u32 p, %4, 0;\n\t"
        "tcgen05.mma.cta_group::1.kind::f16 [%0], %1, %2, %3, {%5,%5,%5,%5}, p;\n\t}"
        :: "r"(d), "l"(ad), "l"(bd_), "r"(IDESC128), "r"(en), "r"(0u) : "memory");
}
#define LDTM32(r, a) asm volatile( \
    "tcgen05.ld.sync.aligned.32x32b.x32.b32 " \
    "{%0,%1,%2,%3,%4,%5,%6,%7,%8,%9,%10,%11,%12,%13,%14,%15," \
    "%16,%17,%18,%19,%20,%21,%22,%23,%24,%25,%26,%27,%28,%29,%30,%31}, [%32];" \
    : "=r"((r)[0]), "=r"((r)[1]), "=r"((r)[2]), "=r"((r)[3]), "=r"((r)[4]), "=r"((r)[5]), \
      "=r"((r)[6]), "=r"((r)[7]), "=r"((r)[8]), "=r"((r)[9]), "=r"((r)[10]), "=r"((r)[11]), \
      "=r"((r)[12]), "=r"((r)[13]), "=r"((r)[14]), "=r"((r)[15]), "=r"((r)[16]), "=r"((r)[17]), \
      "=r"((r)[18]), "=r"((r)[19]), "=r"((r)[20]), "=r"((r)[21]), "=r"((r)[22]), "=r"((r)[23]), \
      "=r"((r)[24]), "=r"((r)[25]), "=r"((r)[26]), "=r"((r)[27]), "=r"((r)[28]), "=r"((r)[29]), \
      "=r"((r)[30]), "=r"((r)[31]) : "r"(a))
#else
#define T5_COMMIT(a)      ((void)0)
#define T5_ALLOC(a, n)    ((void)0)
#define T5_DEALLOC(t, n)  ((void)0)
#define T5_WAIT_LD()      ((void)0)
#define T5_FENCE_B()      ((void)0)
#define T5_FENCE_A()      ((void)0)
__device__ __forceinline__ void mma_ss(u32, u64, u64, u32) {}
#define LDTM32(r, a) do { _Pragma("unroll") for (int _i = 0; _i < 32; ++_i) (r)[_i] = 0u; } while (0)
#endif

// ---------------- activations ----------------
__device__ __forceinline__ float sigf(float x) {
    float e = __expf(-x); return __fdividef(1.f, 1.f + e);
}
__device__ __forceinline__ float tanhf_fast(float x) {
    float ax = fabsf(x);
    float e = __expf(-2.f * ax);
    float t = __fdividef(1.f - e, 1.f + e);
    return copysignf(t, x);
}
__device__ __forceinline__ float tanha(float x) {
    float r; asm("tanh.approx.f32 %0, %1;" : "=f"(r) : "f"(x)); return r;
}
__device__ __forceinline__ float siga(float x) {
    return fmaf(tanha(x * 0.5f), 0.5f, 0.5f);
}
__device__ __forceinline__ u32 pack_hl(float a, float b, u32& lo) {
    __nv_bfloat162 hp, lp;
    hp.x = __float2bfloat16(a); hp.y = __float2bfloat16(b);
    lp.x = __float2bfloat16(a - __bfloat162float(hp.x));
    lp.y = __float2bfloat16(b - __bfloat162float(hp.y));
    lo = *(u32*)&lp;
    return *(u32*)&hp;
}

// ======================= prep kernel (384 blocks + probe) ==================
__global__ void prep(const float* __restrict__ Whh0, const float* __restrict__ Wih1,
                     const float* __restrict__ Whh1, const float* __restrict__ Wd0,
                     const float* __restrict__ Wd1,  const float* __restrict__ Wd2,
                     const float* __restrict__ Wih0, const float* __restrict__ b0,
                     const float* __restrict__ b1)
{
    const int m = blockIdx.x >> 6;         // matrix 0..5
    const int slice = blockIdx.x & 63;     // 1/64 of the matrix
    const float* Ws[6] = {Whh0, Wih1, Whh1, Wd0, Wd1, Wd2};
    const float* W = Ws[m];
    unsigned char* dst = g_wscr + (size_t)m * 256u * 1024u;
    const bool lstm = (m < 3);
    const int base = slice * 1024;
    for (int ii = threadIdx.x; ii < 1024; ii += blockDim.x) {
        int idx = base + ii;
        float v = W[idx];
        __nv_bfloat16 hi = __float2bfloat16(v);
        __nv_bfloat16 lo = __float2bfloat16(v - __bfloat162float(hi));
        u32 slabpair, byte;
        if (lstm) {
            int gc = idx >> 7, k = idx & 127;
            int g = gc >> 7, u = gc & 127;
            int np = 4 * u + g;
            int nh = np >> 8, r = np & 255;
            int kc = k >> 6, kk = k & 63;
            slabpair = (u32)(kc * 4 + nh * 2);
            byte = (u32)(r * 128 + kk * 2);
        } else {
            int n = idx >> 8, k = idx & 255;
            int kc = k >> 6, kk = k & 63;
            slabpair = (u32)(kc * 2);
            byte = (u32)(n * 128 + kk * 2);
        }
        u32 sw = swz(byte);
        *(__nv_bfloat16*)(dst + (size_t)slabpair * 32768u + sw) = hi;
        *(__nv_bfloat16*)(dst + (size_t)(slabpair + 1) * 32768u + sw) = lo;
    }
    if (m == 0 && slice == 0) {
        if (threadIdx.x == 0) g_use_tc = HAS_TC;
        for (int i = threadIdx.x; i < 512; i += blockDim.x) {
            int g = i >> 7, u = i & 127, np = 4 * u + g;
            g_b0p[np] = b0[i];
            g_wih0p[np] = Wih0[i];
            g_b1p[np] = b1[i];
        }
    }
}

// ============ half-slab (16KB) source decoders (j = half-slab idx) =========
__device__ __forceinline__ u64 l0_src(int j) {
    int half = j & 1, hl = (j >> 1) & 1, kc = (j >> 2) & 1, nh = j >> 3;
    return (u64)(uintptr_t)(g_wscr + (size_t)(kc * 4 + nh * 2 + hl) * 32768u
                            + (size_t)half * SLAB);
}
__device__ __forceinline__ u64 l1_src(int j, int nm) {
    int half = j & 1, hl = (j >> 1) & 1;
    int m = (j >> 2) & (nm - 1);
    int mb = (nm == 2) ? 1 : 0;
    int kc = (j >> (2 + mb)) & 1, nh = j >> (3 + mb);
    return (u64)(uintptr_t)(g_wscr + (size_t)(m ? 2 : 1) * 262144u
                            + (size_t)(kc * 4 + nh * 2 + hl) * 32768u
                            + (size_t)half * SLAB);
}
__device__ __forceinline__ u64 dn_src(int j, int l) {
    int half = j & 1, hl = (j >> 1) & 1, kc = j >> 2;
    return (u64)(uintptr_t)(g_wscr + (size_t)(3 + l) * 262144u
                            + (size_t)(kc * 2 + hl) * 32768u
                            + (size_t)half * SLAB);
}

// ======================= consumer (MMA) state ==============================
struct CS { u32 mb, bbuf; int fph[4], iseq; };
__device__ __forceinline__ void issue_slab(CS& cs, u64 ad, u32 dst, int hl, bool first) {
    int s = cs.iseq & 3; cs.iseq++;
    MBAR_WAIT(cs.mb + 8 * s, (u32)cs.fph[s]); cs.fph[s] ^= 1;
    u64 bd = mkdesc(cs.bbuf + (u32)s * SLAB);
    #pragma unroll
    for (int ks = 0; ks < 4; ++ks) {
        u32 en = (ks == 0 && first) ? 0u : 1u;
        mma_ss(dst, ad + (u64)(ks * 2), bd + (u64)(ks * 2), en);
        if (hl == 0)
            mma_ss(dst, ad + 4096u + (u64)(ks * 2), bd + (u64)(ks * 2), 1u);
    }
    T5_COMMIT(cs.mb + 32 + 8 * s);
}

// ======================= producer (TMA) state ==============================
struct PRS { u32 mb, bbuf; int eph[4], used[4], sseq; };
__device__ __forceinline__ void stage_src(PRS& pr, u64 src) {
    int s = pr.sseq & 3; pr.sseq++;
    if (pr.used[s]) { MBAR_WAIT(pr.mb + 32 + 8 * s, (u32)pr.eph[s]); pr.eph[s] ^= 1; }
    pr.used[s] = 1;
    MBAR_EXPECT(pr.mb + 8 * s, SLAB);
    BULKCP(pr.bbuf + (u32)s * SLAB, src, pr.mb + 8 * s);
}

// ======================= tcgen05 fused kernel ==============================
__global__ void __launch_bounds__(544, 1) fused_net(
    const float* __restrict__ x, const float* __restrict__ y,
    const float* __restrict__ bd0, const float* __restrict__ bd1,
    const float* __restrict__ bd2, const float* __restrict__ Wo,
    const float* __restrict__ bo, float* __restrict__ out)
{
#if HAS_TC
    extern __shared__ __align__(1024) unsigned char smem[];
    const u32 sb = smem_u32(smem);
    const int tid = threadIdx.x;
    const int wrp = tid >> 5, lane = tid & 31;
    const bool isOrch = (wrp == 16);
    const int sp = wrp & 3, cho = (wrp >> 2) & 3;
    const int row_l = sp * 32 + lane;
    const int row0 = blockIdx.x * 128;
    const int grow = row0 + row_l;
    float* smf = (float*)smem;
    const bool lo_half = (cho < 2);

    const u32 mb = sb + OFF_MB;
    const u32 gdA = mb + 64, gdB = mb + 72, epL = mb + 80, epH = mb + 88;

    if (tid == 0) {
        for (int i = 0; i < 8; ++i) MBAR_INIT(mb + 8 * i, 1);   // full0..3, empty0..3
        MBAR_INIT(gdA, 1); MBAR_INIT(gdB, 1);
        MBAR_INIT(epL, 8); MBAR_INIT(epH, 8);
    }
    if (wrp == 0) T5_ALLOC(sb + OFF_TMEM, 512);
    if (tid < 512) {
        smf[(OFF_B0P >> 2) + tid] = g_b0p[tid];
        smf[(OFF_WIH >> 2) + tid] = g_wih0p[tid];
        smf[(OFF_B1P >> 2) + tid] = g_b1p[tid];
    }
    if (tid < 256) {
        smf[(OFF_BD >> 2) + tid] = bd0[tid];
        smf[(OFF_BD >> 2) + 256 + tid] = bd1[tid];
        smf[(OFF_BD >> 2) + 512 + tid] = bd2[tid];
    }
    for (int i = tid; i < 1024; i += 544) smf[(OFF_WO >> 2) + i] = Wo[i];
    if (tid < 4) smf[(OFF_BO >> 2) + tid] = bo[tid];
    __syncthreads();
    u32 tmem; asm volatile("ld.shared.b32 %0, [%1];" : "=r"(tmem) : "r"(sb + OFF_TMEM));

    const u64 dH0hi = mkdesc(sb + A_H0HI);
    const u64 dH1hi = mkdesc(sb + A_H1HI);
    const u64 dAhi  = mkdesc(sb + OFF_AREG);

    if (isOrch) {
        if (lane == 1) {
            // ============== TMA producer (warp 16, lane 1) ================
            PRS pr; pr.mb = mb; pr.bbuf = sb + OFF_BBUF;
            pr.eph[0] = pr.eph[1] = pr.eph[2] = pr.eph[3] = 0;
            pr.used[0] = pr.used[1] = pr.used[2] = pr.used[3] = 0;
            pr.sseq = 0;
            for (int t = 0; t < 6; ++t) {
                if (t > 0)
                    for (int j = 0; j < 16; ++j) stage_src(pr, l0_src(j));
                const int nm = (t > 0) ? 2 : 1;
                for (int j = 0; j < 16 * nm; ++j) stage_src(pr, l1_src(j, nm));
            }
            for (int l = 0; l < 3; ++l)
                for (int j = 0; j < 16; ++j) stage_src(pr, dn_src(j, l));
        } else if (lane == 0) {
            // ============== MMA consumer (warp 16, lane 0) ================
            CS cs; cs.mb = mb; cs.bbuf = sb + OFF_BBUF;
            cs.fph[0] = cs.fph[1] = cs.fph[2] = cs.fph[3] = 0;
            cs.iseq = 0;
            int ephL = 0, ephH = 0;

            for (int t = 0; t < 6; ++t) {
                if (t > 0) {   // ---- layer 0 GEMM ----
                    MBAR_WAIT(epL, (u32)ephL); ephL ^= 1;
                    for (int j = 0; j < 16; ++j) {
                        if (j == 8) { T5_COMMIT(gdA); MBAR_WAIT(epH, (u32)ephH); ephH ^= 1; }
                        int half = j & 1, hl = (j >> 1) & 1, kc = (j >> 2) & 1, nh = j >> 3;
                        issue_slab(cs, dH0hi + (u64)(kc * 1024),
                                   tmem + (u32)(nh * 256 + half * 128),
                                   hl, ((j >> 1) & 3) == 0);
                    }
                    T5_COMMIT(gdB);
                }
                {   // ---- layer 1 GEMM ----
                    const int nm = (t > 0) ? 2 : 1, n = 16 * nm;
                    const int mbit = (nm == 2) ? 1 : 0;
                    MBAR_WAIT(epL, (u32)ephL); ephL ^= 1;
                    for (int j = 0; j < n; ++j) {
                        if (j == 4 * nm) { MBAR_WAIT(epH, (u32)ephH); ephH ^= 1; }
                        if (j == 8 * nm) { T5_COMMIT(gdA); }
                        int half = j & 1, hl = (j >> 1) & 1;
                        int m = (j >> 2) & (nm - 1);
                        int kc = (j >> (2 + mbit)) & 1, nh = j >> (3 + mbit);
                        bool first = (hl == 0 && m == 0 && kc == 0);
                        issue_slab(cs, (m ? dH1hi : dH0hi) + (u64)(kc * 1024),
                                   tmem + (u32)(nh * 256 + half * 128), hl, first);
                    }
                    T5_COMMIT(gdB);
                }
            }
            for (int l = 0; l < 3; ++l) {   // ---- dense GEMMs ----
                MBAR_WAIT(epL, (u32)ephL); ephL ^= 1;
                MBAR_WAIT(epH, (u32)ephH); ephH ^= 1;
                for (int j = 0; j < 16; ++j) {
                    int half = j & 1, hl = (j >> 1) & 1, kc = j >> 2;
                    issue_slab(cs, dAhi + (u64)(kc * 1024),
                               tmem + (u32)(half * 128), hl, j < 2);
                }
                T5_COMMIT(gdB);
            }
        }
    } else {
        // =================== compute warps (0..15) ========================
        int gphA = 0, gphB = 0;
        const float xn = 2.f * x[grow] - 1.f, yn = 2.f * y[grow] - 1.f;
        const u32 tm_lane = tmem + ((u32)sp << 21);

        for (int t = 0; t < 6; ++t) {
            // ---------- layer 0 epilogue ----------
            {
                const bool hasg = (t > 0);
                float ft;
                if      (t == 0) ft = xn;
                else if (t == 1) ft = yn;
                else if (t == 2) ft = xn + yn;
                else if (t == 3) ft = xn - yn;
                else if (t == 4) ft = xn * yn;
                else             ft = xn * xn + yn * yn;
                if (hasg) {
                    if (lo_half) { MBAR_WAIT(gdA, (u32)gphA); }
                    gphA ^= 1;
                    if (!lo_half) { MBAR_WAIT(gdB, (u32)gphB); }
                    T5_FENCE_A();
                }
                u32 oh[16], ol[16];
                #pragma unroll
                for (int ch = 0; ch < 4; ++ch) {
                    const int cb = 128 * cho + 32 * ch;
                    const int u0 = 32 * cho + 8 * ch;
                    float co[8];
                    #pragma unroll
                    for (int jj = 0; jj < 8; ++jj)
                        co[jj] = hasg ? g_c0[(size_t)(u0 + jj) * NS + grow] : 0.f;
                    u32 r[32];
                    if (hasg) { LDTM32(r, tm_lane + (u32)cb); T5_WAIT_LD(); }
                    #pragma unroll
                    for (int j = 0; j < 8; j += 2) {
                        float h2[2];
                        #pragma unroll
                        for (int q = 0; q < 2; ++q) {
                            const int col = cb + 4 * (j + q);
                            float gi = smf[(OFF_B0P >> 2) + col]     + ft * smf[(OFF_WIH >> 2) + col];
                            float gf = smf[(OFF_B0P >> 2) + col + 1] + ft * smf[(OFF_WIH >> 2) + col + 1];
                            float gg = smf[(OFF_B0P >> 2) + col + 2] + ft * smf[(OFF_WIH >> 2) + col + 2];
                            float go = smf[(OFF_B0P >> 2) + col + 3] + ft * smf[(OFF_WIH >> 2) + col + 3];
                            if (hasg) {
                                gi += __uint_as_float(r[4 * (j + q)]);
                                gf += __uint_as_float(r[4 * (j + q) + 1]);
                                gg += __uint_as_float(r[4 * (j + q) + 2]);
                                go += __uint_as_float(r[4 * (j + q) + 3]);
                            }
                            float cn = siga(gf) * co[j + q] + siga(gi) * tanha(gg);
                            float hn = siga(go) * tanha(cn);
                            g_c0[(size_t)(u0 + j + q) * NS + grow] = cn;
                            h2[q] = hn;
                        }
                        oh[ch * 4 + (j >> 1)] = pack_hl(h2[0], h2[1], ol[ch * 4 + (j >> 1)]);
                    }
                }
                if (hasg) {
                    if (lo_half) { MBAR_WAIT(gdB, (u32)gphB); }
                    gphB ^= 1;
                }
                #pragma unroll
                for (int ch = 0; ch < 4; ++ch)
                    #pragma unroll
                    for (int jp = 0; jp < 4; ++jp) {
                        int u = 32 * cho + 8 * ch + 2 * jp;
                        u32 base = (u32)((u >> 6) * 16384) + swz((u32)(row_l * 128 + (u & 63) * 2));
                        *(u32*)(smem + A_H0HI + base) = oh[ch * 4 + jp];
                        *(u32*)(smem + A_H0LO + base) = ol[ch * 4 + jp];
                    }
                FENCE_ASYNC();
                __syncwarp();
                if (lane == 0) MBAR_ARRIVE(lo_half ? epL : epH);
            }
            // ---------- layer 1 epilogue ----------
            {
                const bool last = (t == 5);
                if (lo_half) { MBAR_WAIT(gdA, (u32)gphA); }
                gphA ^= 1;
                if (!lo_half || last) { MBAR_WAIT(gdB, (u32)gphB); }
                T5_FENCE_A();
                u32 oh[16], ol[16];
                #pragma unroll
                for (int ch = 0; ch < 4; ++ch) {
                    const int cb = 128 * cho + 32 * ch;
                    const int u0 = 32 * cho + 8 * ch;
                    float co[8], hsv[8];
                    #pragma unroll
                    for (int jj = 0; jj < 8; ++jj) {
                        co[jj]  = (t > 0) ? g_c1[(size_t)(u0 + jj) * NS + grow] : 0.f;
                        hsv[jj] = (t > 0) ? g_hs[(size_t)(u0 + jj) * NS + grow] : 0.f;
                    }
                    u32 r[32];
                    LDTM32(r, tm_lane + (u32)cb); T5_WAIT_LD();
                    #pragma unroll
                    for (int j = 0; j < 8; j += 2) {
                        float h2[2], m2[2];
                        #pragma unroll
                        for (int q = 0; q < 2; ++q) {
                            const int col = cb + 4 * (j + q);
                            float gi = __uint_as_float(r[4 * (j + q)])     + smf[(OFF_B1P >> 2) + col];
                            float gf = __uint_as_float(r[4 * (j + q) + 1]) + smf[(OFF_B1P >> 2) + col + 1];
                            float gg = __uint_as_float(r[4 * (j + q) + 2]) + smf[(OFF_B1P >> 2) + col + 2];
                            float go = __uint_as_float(r[4 * (j + q) + 3]) + smf[(OFF_B1P >> 2) + col + 3];
                            float cn = siga(gf) * co[j + q] + siga(gi) * tanha(gg);
                            float hn = siga(go) * tanha(cn);
                            g_c1[(size_t)(u0 + j + q) * NS + grow] = cn;
                            float s = hsv[j + q] + hn;
                            if (!last) g_hs[(size_t)(u0 + j + q) * NS + grow] = s;
                            h2[q] = hn;
                            m2[q] = s * (1.f / 6.f);
                        }
                        const int jp = j >> 1;
                        oh[ch * 4 + jp] = pack_hl(h2[0], h2[1], ol[ch * 4 + jp]);
                        if (last) {
                            int u = u0 + j;
                            u32 base = (u32)((u >> 6) * 16384) + swz((u32)(row_l * 128 + (u & 63) * 2));
                            *(u32*)(smem + A_H1HI + base) = oh[ch * 4 + jp];
                            *(u32*)(smem + A_H1LO + base) = ol[ch * 4 + jp];
                            u32 mlo; u32 mhi = pack_hl(m2[0], m2[1], mlo);
                            *(u32*)(smem + A_H0HI + base) = mhi;   // mean = feat k[128,256)
                            *(u32*)(smem + A_H0LO + base) = mlo;
                        }
                    }
                }
                if (!last) {
                    if (lo_half) { MBAR_WAIT(gdB, (u32)gphB); }
                    gphB ^= 1;
                    #pragma unroll
                    for (int ch = 0; ch < 4; ++ch)
                        #pragma unroll
                        for (int jp = 0; jp < 4; ++jp) {
                            int u = 32 * cho + 8 * ch + 2 * jp;
                            u32 base = (u32)((u >> 6) * 16384) + swz((u32)(row_l * 128 + (u & 63) * 2));
                            *(u32*)(smem + A_H1HI + base) = oh[ch * 4 + jp];
                            *(u32*)(smem + A_H1LO + base) = ol[ch * 4 + jp];
                        }
                } else {
                    gphB ^= 1;
                }
                FENCE_ASYNC();
                __syncwarp();
                if (lane == 0) MBAR_ARRIVE(lo_half ? epL : epH);
            }
        }
        // ---------- dense epilogues ----------
        for (int l = 0; l < 3; ++l) {
            MBAR_WAIT(gdB, (u32)gphB); gphB ^= 1;
            T5_FENCE_A();
            const bool fin = (l == 2);
            #pragma unroll
            for (int ch = 0; ch < 2; ++ch) {
                const int cb = 64 * cho + 32 * ch;
                u32 r[32];
                LDTM32(r, tm_lane + (u32)cb); T5_WAIT_LD();
                #pragma unroll
                for (int j = 0; j < 32; j += 2) {
                    int n = cb + j;
                    float a0 = tanha(__uint_as_float(r[j])     + smf[(OFF_BD >> 2) + l * 256 + n]);
                    float a1 = tanha(__uint_as_float(r[j + 1]) + smf[(OFF_BD >> 2) + l * 256 + n + 1]);
                    if (!fin) {
                        u32 base = (u32)((n >> 6) * 16384) + swz((u32)(row_l * 128 + (n & 63) * 2));
                        u32 lo; u32 hi = pack_hl(a0, a1, lo);
                        *(u32*)(smem + OFF_AREG + base) = hi;
                        *(u32*)(smem + OFF_AREG + 65536 + base) = lo;
                    } else {
                        int n2 = n ^ ((row_l & 7) << 2);   // fp32, bank-swizzled
                        *(float2*)(smf + (OFF_AREG >> 2) + row_l * 256 + n2) = make_float2(a0, a1);
                    }
                }
            }
            if (!fin) {
                FENCE_ASYNC();
                __syncwarp();
                if (lane == 0) MBAR_ARRIVE(lo_half ? epL : epH);
            }
        }
    }

    __syncthreads();

    // ---------- output head ----------
    if (tid < 512) {
        const int rh = tid >> 2, o = tid & 3;
        const float* wo = smf + (OFF_WO >> 2) + o * 256;
        const float* arow = smf + (OFF_AREG >> 2) + rh * 256;
        const int s = (rh & 7) << 2;
        float s0 = 0.f, s1 = 0.f, s2 = 0.f, s3 = 0.f;
        #pragma unroll 8
        for (int kb = 0; kb < 64; ++kb) {
            int k = kb * 4;
            float4 v = *(const float4*)(arow + (k ^ s));
            s0 += v.x * wo[k];
            s1 += v.y * wo[k + 1];
            s2 += v.z * wo[k + 2];
            s3 += v.w * wo[k + 3];
        }
        out[(size_t)(row0 + rh) * 4 + o] = ((s0 + s1) + (s2 + s3)) + smf[(OFF_BO >> 2) + o];
    }

    __syncthreads();
    if (wrp == 0) T5_DEALLOC(tmem, 512);
#endif  // HAS_TC
}

// ============== compact fallback (never taken when tcgen05 exists) =========
__global__ void fb_net(
    const float* __restrict__ x, const float* __restrict__ y,
    const float* __restrict__ Wih0, const float* __restrict__ Whh0, const float* __restrict__ b0,
    const float* __restrict__ Wih1, const float* __restrict__ Whh1, const float* __restrict__ b1,
    const float* __restrict__ Wd0, const float* __restrict__ bd0,
    const float* __restrict__ Wd1, const float* __restrict__ bd1,
    const float* __restrict__ Wd2, const float* __restrict__ bd2,
    const float* __restrict__ Wo,  const float* __restrict__ bo,
    float* __restrict__ out)
{
    if (g_use_tc) return;
    __shared__ float h0[128], c0[128], h1[128], c1[128], hs[128], feat[256], buf[2][256];
    const int u = threadIdx.x;
    for (int s = blockIdx.x; s < NS; s += gridDim.x) {
        float xn = 2.f * x[s] - 1.f, yn = 2.f * y[s] - 1.f;
        h0[u] = c0[u] = h1[u] = c1[u] = hs[u] = 0.f;
        __syncthreads();
        for (int t = 0; t < 6; ++t) {
            float ft = (t == 0) ? xn : (t == 1) ? yn : (t == 2) ? xn + yn
                     : (t == 3) ? xn - yn : (t == 4) ? xn * yn : xn * xn + yn * yn;
            float g[4];
            for (int gi = 0; gi < 4; ++gi) {
                int row = gi * 128 + u;
                float acc = b0[row] + Wih0[row] * ft;
                for (int k = 0; k < 128; ++k) acc += Whh0[row * 128 + k] * h0[k];
                g[gi] = acc;
            }
            float cn = sigf(g[1]) * c0[u] + sigf(g[0]) * tanhf_fast(g[2]);
            float hn = sigf(g[3]) * tanhf_fast(cn);
            __syncthreads();
            c0[u] = cn; h0[u] = hn;
            __syncthreads();
            for (int gi = 0; gi < 4; ++gi) {
                int row = gi * 128 + u;
                float acc = b1[row];
                for (int k = 0; k < 128; ++k)
                    acc += Wih1[row * 128 + k] * h0[k] + Whh1[row * 128 + k] * h1[k];
                g[gi] = acc;
            }
            cn = sigf(g[1]) * c1[u] + sigf(g[0]) * tanhf_fast(g[2]);
            hn = sigf(g[3]) * tanhf_fast(cn);
            __syncthreads();
            c1[u] = cn; h1[u] = hn; hs[u] += hn;
            __syncthreads();
        }
        feat[u] = h1[u]; feat[128 + u] = hs[u] * (1.f / 6.f);
        __syncthreads();
        const float* cur = feat;
        for (int l = 0; l < 3; ++l) {
            const float* W = (l == 0) ? Wd0 : (l == 1) ? Wd1 : Wd2;
            const float* bb = (l == 0) ? bd0 : (l == 1) ? bd1 : bd2;
            float* nxt = buf[l & 1];
            for (int n = u; n < 256; n += 128) {
                float acc = bb[n];
                for (int k = 0; k < 256; ++k) acc += W[n * 256 + k] * cur[k];
                nxt[n] = tanhf_fast(acc);
            }
            __syncthreads();
            cur = nxt;
        }
        if (u < 4) {
            float acc = bo[u];
            for (int k = 0; k < 256; ++k) acc += Wo[u * 256 + k] * cur[k];
            out[(size_t)s * 4 + u] = acc;
        }
        __syncthreads();
    }
}

// ======================= host launcher =====================================
extern "C" void kernel_launch(void* const* d_in, const int* in_sizes, int n_in,
                              void* d_out, int out_size)
{
    const float* x    = (const float*)d_in[0];
    const float* y    = (const float*)d_in[1];
    const float* Wih0 = (const float*)d_in[2];
    const float* Whh0 = (const float*)d_in[3];
    const float* b0   = (const float*)d_in[4];
    const float* Wih1 = (const float*)d_in[5];
    const float* Whh1 = (const float*)d_in[6];
    const float* b1   = (const float*)d_in[7];
    const float* Wd0  = (const float*)d_in[8];
    const float* bd0  = (const float*)d_in[9];
    const float* Wd1  = (const float*)d_in[10];
    const float* bd1  = (const float*)d_in[11];
    const float* Wd2  = (const float*)d_in[12];
    const float* bd2  = (const float*)d_in[13];
    const float* Wo   = (const float*)d_in[14];
    const float* bo   = (const float*)d_in[15];
    float* out = (float*)d_out;

    prep<<<384, 256>>>(Whh0, Wih1, Whh1, Wd0, Wd1, Wd2, Wih0, b0, b1);

    cudaFuncSetAttribute(fused_net, cudaFuncAttributeMaxDynamicSharedMemorySize, SMEM_BYTES);
    fused_net<<<NS / 128, 544, SMEM_BYTES>>>(x, y, bd0, bd1, bd2, Wo, bo, out);

    fb_net<<<512, 128>>>(x, y, Wih0, Whh0, b0, Wih1, Whh1, b1,
                         Wd0, bd0, Wd1, bd1, Wd2, bd2, Wo, bo, out);
}

// round 15
// speedup vs baseline: 1.6908x; 1.6908x over previous
#include <cuda_runtime.h>
#include <cuda_bf16.h>
#include <cstdint>
#include <math.h>

#define NS 65536
typedef uint32_t u32;
typedef uint64_t u64;

// ===== arch-specific feature gate (tcgen05 only exists on sm_103a pass) ====
#if defined(__CUDA_ARCH__) && (defined(__CUDA_ARCH_FEAT_SM103_ALL) || \
    (defined(__CUDA_ARCH_SPECIFIC__) && (__CUDA_ARCH_SPECIFIC__ == 1030)) || \
    (defined(__CUDA_ARCH_FAMILY_SPECIFIC__) && (__CUDA_ARCH_FAMILY_SPECIFIC__ == 1030)))
#define HAS_TC 1
#else
#define HAS_TC 0
#endif

// ======================= global scratch (no runtime alloc) =================
__device__ __align__(256) unsigned char g_wscr[6u * 256u * 1024u];
__device__ float g_b0p[512], g_wih0p[512], g_b1p[512];
__device__ float g_c0[128u * NS];
__device__ float g_c1[128u * NS];
__device__ float g_hs[128u * NS];
__device__ int   g_use_tc;

__host__ __device__ __forceinline__ u32 swz(u32 b) { return b ^ ((b >> 3) & 0x70); }

// ======================= smem map (bytes) ==================================
#define OFF_TMEM   0
#define OFF_B0P    64
#define OFF_WIH    2112
#define OFF_B1P    4160
#define OFF_BD     6208
#define OFF_WO     9280
#define OFF_BO     13376
#define OFF_MB     13440  // full0,full1,empty0,empty1,gdA,gdB,epL,epH,tmL,tmH
#define OFF_BBUF   16384  // 2 x 32KB
#define OFF_AREG   81920  // 128KB
#define SMEM_BYTES 212992
#define A_H1HI (OFF_AREG)
#define A_H0HI (OFF_AREG + 32768)
#define A_H1LO (OFF_AREG + 65536)
#define A_H0LO (OFF_AREG + 98304)

#define IDESC 0x8400490u  // f32 accum, bf16xbf16, M=128, N=256
static __device__ __forceinline__ u64 mkdesc(u32 smem_addr) {
    return (u64(2) << 61) | (u64(1) << 46) | (u64(64) << 32) | (u64(1) << 16)
         | ((u64)(smem_addr >> 4) & 0x3FFF);
}

// ======================= PTX helpers =======================================
__device__ __forceinline__ u32 smem_u32(const void* p) {
    u32 a; asm("{ .reg .u64 t; cvta.to.shared.u64 t, %1; cvt.u32.u64 %0, t; }" : "=r"(a) : "l"(p));
    return a;
}
#define MBAR_INIT(a, c) asm volatile("mbarrier.init.shared.b64 [%0], %1;" :: "r"(a), "r"(c) : "memory")
#define MBAR_EXPECT(a, b) asm volatile("mbarrier.arrive.expect_tx.shared.b64 _, [%0], %1;" :: "r"(a), "r"(b) : "memory")
#define MBAR_ARRIVE(a) asm volatile("mbarrier.arrive.release.cta.shared::cta.b64 _, [%0];" :: "r"(a) : "memory")
#define MBAR_WAIT(a, ph) do { \
    asm volatile("{\n\t.reg .pred P;\n\tWL%=:\n\t" \
        "mbarrier.try_wait.parity.acquire.cta.shared::cta.b64 P, [%0], %1, 0x989680;\n\t" \
        "@P bra.uni WD%=;\n\tbra.uni WL%=;\n\tWD%=:\n\t}" \
        :: "r"(a), "r"(ph) : "memory"); } while (0)
#define BULKCP(dst, src, mbar) asm volatile( \
    "cp.async.bulk.shared::cluster.global.mbarrier::complete_tx::bytes [%0], [%1], %2, [%3];" \
    :: "r"(dst), "l"(src), "r"(32768u), "r"(mbar) : "memory")
#define FENCE_ASYNC() asm volatile("fence.proxy.async.shared::cta;" ::: "memory")

#if HAS_TC
#define T5_COMMIT(a) asm volatile( \
    "tcgen05.commit.cta_group::1.mbarrier::arrive::one.shared::cluster.b64 [%0];" :: "r"(a) : "memory")
#define T5_ALLOC(a, n) asm volatile( \
    "tcgen05.alloc.cta_group::1.sync.aligned.shared::cta.b32 [%0], %1;" :: "r"(a), "r"(n) : "memory")
#define T5_DEALLOC(t, n) asm volatile( \
    "tcgen05.dealloc.cta_group::1.sync.aligned.b32 %0, %1;" :: "r"(t), "r"(n))
#define T5_WAIT_LD() asm volatile("tcgen05.wait::ld.sync.aligned;" ::: "memory")
#define T5_FENCE_B() asm volatile("tcgen05.fence::before_thread_sync;" ::: "memory")
#define T5_FENCE_A() asm volatile("tcgen05.fence::after_thread_sync;" ::: "memory")
__device__ __forceinline__ void mma_ss(u32 d, u64 ad, u64 bd_, u32 en) {
    asm volatile(
        "{\n\t.reg .pred p;\n\tsetp.ne.u32 p, %4, 0;\n\t"
        "tcgen05.mma.cta_group::1.kind::f16 [%0], %1, %2, %3, {%5,%5,%5,%5}, p;\n\t}"
        :: "r"(d), "l"(ad), "l"(bd_), "r"(IDESC), "r"(en), "r"(0u) : "memory");
}
#define LDTM32(r, a) asm volatile( \
    "tcgen05.ld.sync.aligned.32x32b.x32.b32 " \
    "{%0,%1,%2,%3,%4,%5,%6,%7,%8,%9,%10,%11,%12,%13,%14,%15," \
    "%16,%17,%18,%19,%20,%21,%22,%23,%24,%25,%26,%27,%28,%29,%30,%31}, [%32];" \
    : "=r"((r)[0]), "=r"((r)[1]), "=r"((r)[2]), "=r"((r)[3]), "=r"((r)[4]), "=r"((r)[5]), \
      "=r"((r)[6]), "=r"((r)[7]), "=r"((r)[8]), "=r"((r)[9]), "=r"((r)[10]), "=r"((r)[11]), \
      "=r"((r)[12]), "=r"((r)[13]), "=r"((r)[14]), "=r"((r)[15]), "=r"((r)[16]), "=r"((r)[17]), \
      "=r"((r)[18]), "=r"((r)[19]), "=r"((r)[20]), "=r"((r)[21]), "=r"((r)[22]), "=r"((r)[23]), \
      "=r"((r)[24]), "=r"((r)[25]), "=r"((r)[26]), "=r"((r)[27]), "=r"((r)[28]), "=r"((r)[29]), \
      "=r"((r)[30]), "=r"((r)[31]) : "r"(a))
#else
#define T5_COMMIT(a)      ((void)0)
#define T5_ALLOC(a, n)    ((void)0)
#define T5_DEALLOC(t, n)  ((void)0)
#define T5_WAIT_LD()      ((void)0)
#define T5_FENCE_B()      ((void)0)
#define T5_FENCE_A()      ((void)0)
__device__ __forceinline__ void mma_ss(u32, u64, u64, u32) {}
#define LDTM32(r, a) do { _Pragma("unroll") for (int _i = 0; _i < 32; ++_i) (r)[_i] = 0u; } while (0)
#endif

// ---------------- activations ----------------
__device__ __forceinline__ float sigf(float x) {
    float e = __expf(-x); return __fdividef(1.f, 1.f + e);
}
__device__ __forceinline__ float tanhf_fast(float x) {
    float ax = fabsf(x);
    float e = __expf(-2.f * ax);
    float t = __fdividef(1.f - e, 1.f + e);
    return copysignf(t, x);
}
__device__ __forceinline__ float tanha(float x) {
    float r; asm("tanh.approx.f32 %0, %1;" : "=f"(r) : "f"(x)); return r;
}
__device__ __forceinline__ float siga(float x) {
    return fmaf(tanha(x * 0.5f), 0.5f, 0.5f);
}
__device__ __forceinline__ u32 pack_hl(float a, float b, u32& lo) {
    __nv_bfloat162 hp, lp;
    hp.x = __float2bfloat16(a); hp.y = __float2bfloat16(b);
    lp.x = __float2bfloat16(a - __bfloat162float(hp.x));
    lp.y = __float2bfloat16(b - __bfloat162float(hp.y));
    lo = *(u32*)&lp;
    return *(u32*)&hp;
}

// ======================= prep kernel (384 blocks + probe) ==================
__global__ void prep(const float* __restrict__ Whh0, const float* __restrict__ Wih1,
                     const float* __restrict__ Whh1, const float* __restrict__ Wd0,
                     const float* __restrict__ Wd1,  const float* __restrict__ Wd2,
                     const float* __restrict__ Wih0, const float* __restrict__ b0,
                     const float* __restrict__ b1)
{
    const int m = blockIdx.x >> 6;
    const int slice = blockIdx.x & 63;
    const float* Ws[6] = {Whh0, Wih1, Whh1, Wd0, Wd1, Wd2};
    const float* W = Ws[m];
    unsigned char* dst = g_wscr + (size_t)m * 256u * 1024u;
    const bool lstm = (m < 3);
    const int base = slice * 1024;
    for (int ii = threadIdx.x; ii < 1024; ii += blockDim.x) {
        int idx = base + ii;
        float v = W[idx];
        __nv_bfloat16 hi = __float2bfloat16(v);
        __nv_bfloat16 lo = __float2bfloat16(v - __bfloat162float(hi));
        u32 slabpair, byte;
        if (lstm) {
            int gc = idx >> 7, k = idx & 127;
            int g = gc >> 7, u = gc & 127;
            int np = 4 * u + g;
            int nh = np >> 8, r = np & 255;
            int kc = k >> 6, kk = k & 63;
            slabpair = (u32)(kc * 4 + nh * 2);
            byte = (u32)(r * 128 + kk * 2);
        } else {
            int n = idx >> 8, k = idx & 255;
            int kc = k >> 6, kk = k & 63;
            slabpair = (u32)(kc * 2);
            byte = (u32)(n * 128 + kk * 2);
        }
        u32 sw = swz(byte);
        *(__nv_bfloat16*)(dst + (size_t)slabpair * 32768u + sw) = hi;
        *(__nv_bfloat16*)(dst + (size_t)(slabpair + 1) * 32768u + sw) = lo;
    }
    if (m == 0 && slice == 0) {
        if (threadIdx.x == 0) g_use_tc = HAS_TC;
        for (int i = threadIdx.x; i < 512; i += blockDim.x) {
            int g = i >> 7, u = i & 127, np = 4 * u + g;
            g_b0p[np] = b0[i];
            g_wih0p[np] = Wih0[i];
            g_b1p[np] = b1[i];
        }
    }
}

// ======================= slab source decoders ==============================
__device__ __forceinline__ u64 l0_src(int j) {
    int nh = j >> 2, kc = (j >> 1) & 1, hl = j & 1;
    return (u64)(uintptr_t)(g_wscr + (size_t)(kc * 4 + nh * 2 + hl) * 32768u);
}
__device__ __forceinline__ u64 l1_src(int j, int nm) {
    int hl = j & 1, tmp = j >> 1;
    int m = tmp % nm; tmp /= nm;
    int kc = tmp & 1, nh = tmp >> 1;
    return (u64)(uintptr_t)(g_wscr + (size_t)(m ? 2 : 1) * 262144u
                            + (size_t)(kc * 4 + nh * 2 + hl) * 32768u);
}
__device__ __forceinline__ u64 dn_src(int j, int l) {
    int hl = j & 1, kc = j >> 1;
    return (u64)(uintptr_t)(g_wscr + (size_t)(3 + l) * 262144u
                            + (size_t)(kc * 2 + hl) * 32768u);
}

// ======================= consumer (MMA) state ==============================
struct CS { u32 fullb[2], emptyb[2], bbuf[2]; int fph[2], iseq; };
__device__ __forceinline__ void issue_slab(CS& cs, u64 ad, u32 dst, int hl, bool first) {
    int s = cs.iseq & 1; cs.iseq++;
    MBAR_WAIT(cs.fullb[s], (u32)cs.fph[s]); cs.fph[s] ^= 1;
    u64 bd = mkdesc(cs.bbuf[s]);
    #pragma unroll
    for (int ks = 0; ks < 4; ++ks) {
        u32 en = (ks == 0 && first) ? 0u : 1u;
        mma_ss(dst, ad + (u64)(ks * 2), bd + (u64)(ks * 2), en);
        if (hl == 0)
            mma_ss(dst, ad + 4096u + (u64)(ks * 2), bd + (u64)(ks * 2), 1u);
    }
    T5_COMMIT(cs.emptyb[s]);
}

// ======================= producer (TMA) state ==============================
struct PRS { u32 fullb[2], emptyb[2], bbuf[2]; int eph[2], used[2], sseq; };
__device__ __forceinline__ void stage_src(PRS& pr, u64 src) {
    int s = pr.sseq & 1; pr.sseq++;
    if (pr.used[s]) { MBAR_WAIT(pr.emptyb[s], (u32)pr.eph[s]); pr.eph[s] ^= 1; }
    pr.used[s] = 1;
    MBAR_EXPECT(pr.fullb[s], 32768u);
    BULKCP(pr.bbuf[s], src, pr.fullb[s]);
}

// ======================= tcgen05 fused kernel ==============================
__global__ void __launch_bounds__(544, 1) fused_net(
    const float* __restrict__ x, const float* __restrict__ y,
    const float* __restrict__ bd0, const float* __restrict__ bd1,
    const float* __restrict__ bd2, const float* __restrict__ Wo,
    const float* __restrict__ bo, float* __restrict__ out)
{
#if HAS_TC
    extern __shared__ __align__(1024) unsigned char smem[];
    const u32 sb = smem_u32(smem);
    const int tid = threadIdx.x;
    const int wrp = tid >> 5, lane = tid & 31;
    const bool isOrch = (wrp == 16);
    const int sp = wrp & 3, cho = (wrp >> 2) & 3;
    const int row_l = sp * 32 + lane;
    const int row0 = blockIdx.x * 128;
    const int grow = row0 + row_l;
    float* smf = (float*)smem;
    const bool lo_half = (cho < 2);

    const u32 fullb0 = sb + OFF_MB,      fullb1 = sb + OFF_MB + 8;
    const u32 emptb0 = sb + OFF_MB + 16, emptb1 = sb + OFF_MB + 24;
    const u32 gdA = sb + OFF_MB + 32, gdB = sb + OFF_MB + 40;
    const u32 epL = sb + OFF_MB + 48, epH = sb + OFF_MB + 56;
    const u32 tmL = sb + OFF_MB + 64, tmH = sb + OFF_MB + 72;

    if (tid == 0) {
        MBAR_INIT(fullb0, 1); MBAR_INIT(fullb1, 1);
        MBAR_INIT(emptb0, 1); MBAR_INIT(emptb1, 1);
        MBAR_INIT(gdA, 1);    MBAR_INIT(gdB, 1);
        MBAR_INIT(epL, 8);    MBAR_INIT(epH, 8);
        MBAR_INIT(tmL, 8);    MBAR_INIT(tmH, 8);
    }
    if (wrp == 0) T5_ALLOC(sb + OFF_TMEM, 512);
    if (tid < 512) {
        smf[(OFF_B0P >> 2) + tid] = g_b0p[tid];
        smf[(OFF_WIH >> 2) + tid] = g_wih0p[tid];
        smf[(OFF_B1P >> 2) + tid] = g_b1p[tid];
    }
    if (tid < 256) {
        smf[(OFF_BD >> 2) + tid] = bd0[tid];
        smf[(OFF_BD >> 2) + 256 + tid] = bd1[tid];
        smf[(OFF_BD >> 2) + 512 + tid] = bd2[tid];
    }
    for (int i = tid; i < 1024; i += 544) smf[(OFF_WO >> 2) + i] = Wo[i];
    if (tid < 4) smf[(OFF_BO >> 2) + tid] = bo[tid];
    __syncthreads();
    u32 tmem; asm volatile("ld.shared.b32 %0, [%1];" : "=r"(tmem) : "r"(sb + OFF_TMEM));

    const u64 dH0hi = mkdesc(sb + A_H0HI);
    const u64 dH1hi = mkdesc(sb + A_H1HI);
    const u64 dAhi  = mkdesc(sb + OFF_AREG);

    if (isOrch) {
        if (lane == 1) {
            // ============== TMA producer (warp 16, lane 1) ================
            PRS pr;
            pr.fullb[0] = fullb0; pr.fullb[1] = fullb1;
            pr.emptyb[0] = emptb0; pr.emptyb[1] = emptb1;
            pr.bbuf[0] = sb + OFF_BBUF; pr.bbuf[1] = sb + OFF_BBUF + 32768;
            pr.eph[0] = pr.eph[1] = 0; pr.used[0] = pr.used[1] = 0; pr.sseq = 0;
            for (int t = 0; t < 6; ++t) {
                if (t > 0)
                    for (int j = 0; j < 8; ++j) stage_src(pr, l0_src(j));
                const int nm = (t > 0) ? 2 : 1;
                for (int j = 0; j < 8 * nm; ++j) stage_src(pr, l1_src(j, nm));
            }
            for (int l = 0; l < 3; ++l)
                for (int j = 0; j < 8; ++j) stage_src(pr, dn_src(j, l));
        } else if (lane == 0) {
            // ============== MMA consumer (warp 16, lane 0) ================
            CS cs;
            cs.fullb[0] = fullb0; cs.fullb[1] = fullb1;
            cs.emptyb[0] = emptb0; cs.emptyb[1] = emptb1;
            cs.bbuf[0] = sb + OFF_BBUF; cs.bbuf[1] = sb + OFF_BBUF + 32768;
            cs.fph[0] = cs.fph[1] = 0; cs.iseq = 0;
            int ephL = 0, ephH = 0, tphL = 0, tphH = 0;

            for (int t = 0; t < 6; ++t) {
                if (t > 0) {   // ---- layer 0 GEMM: needs TMEM free only ----
                    MBAR_WAIT(tmL, (u32)tphL); tphL ^= 1;
                    for (int j = 0; j < 8; ++j) {
                        if (j == 4) { T5_COMMIT(gdA); MBAR_WAIT(tmH, (u32)tphH); tphH ^= 1; }
                        int nh = j >> 2, kc = (j >> 1) & 1, hl = j & 1;
                        issue_slab(cs, dH0hi + (u64)(kc * 1024), tmem + (u32)(nh * 256),
                                   hl, (j & 3) == 0);
                    }
                    T5_COMMIT(gdB);
                }
                {   // ---- layer 1 GEMM: needs h0 stores (epL/epH) ----
                    const int nm = (t > 0) ? 2 : 1, n = 8 * nm;
                    MBAR_WAIT(epL, (u32)ephL); ephL ^= 1;
                    for (int j = 0; j < n; ++j) {
                        if (j == 2 * nm) { MBAR_WAIT(epH, (u32)ephH); ephH ^= 1; }
                        if (j == 4 * nm) { T5_COMMIT(gdA); }
                        int hl = j & 1, tmp = j >> 1;
                        int m = tmp % nm; tmp /= nm;
                        int kc = tmp & 1, nh = tmp >> 1;
                        issue_slab(cs, (m ? dH1hi : dH0hi) + (u64)(kc * 1024),
                                   tmem + (u32)(nh * 256), hl,
                                   (j == 0 || j == 4 * nm));
                    }
                    T5_COMMIT(gdB);
                }
            }
            for (int l = 0; l < 3; ++l) {   // ---- dense GEMMs ----
                MBAR_WAIT(epL, (u32)ephL); ephL ^= 1;
                MBAR_WAIT(epH, (u32)ephH); ephH ^= 1;
                for (int j = 0; j < 8; ++j) {
                    int hl = j & 1, kc = j >> 1;
                    issue_slab(cs, dAhi + (u64)(kc * 1024), tmem, hl, j == 0);
                }
                T5_COMMIT(gdB);
            }
        }
    } else {
        // =================== compute warps (0..15) ========================
        int gphA = 0, gphB = 0;
        const float xn = 2.f * x[grow] - 1.f, yn = 2.f * y[grow] - 1.f;
        const u32 tm_lane = tmem + ((u32)sp << 21);

        for (int t = 0; t < 6; ++t) {
            // ---------- layer 0 epilogue (arrives epL/epH) ----------
            {
                const bool hasg = (t > 0);
                float ft;
                if      (t == 0) ft = xn;
                else if (t == 1) ft = yn;
                else if (t == 2) ft = xn + yn;
                else if (t == 3) ft = xn - yn;
                else if (t == 4) ft = xn * yn;
                else             ft = xn * xn + yn * yn;
                if (hasg) {
                    if (lo_half) { MBAR_WAIT(gdA, (u32)gphA); }
                    gphA ^= 1;
                    if (!lo_half) { MBAR_WAIT(gdB, (u32)gphB); }
                    T5_FENCE_A();
                }
                u32 oh[16], ol[16];
                #pragma unroll
                for (int ch = 0; ch < 4; ++ch) {
                    const int cb = 128 * cho + 32 * ch;
                    const int u0 = 32 * cho + 8 * ch;
                    float co[8];
                    #pragma unroll
                    for (int jj = 0; jj < 8; ++jj)
                        co[jj] = hasg ? g_c0[(size_t)(u0 + jj) * NS + grow] : 0.f;
                    u32 r[32];
                    if (hasg) { LDTM32(r, tm_lane + (u32)cb); T5_WAIT_LD(); }
                    #pragma unroll
                    for (int j = 0; j < 8; j += 2) {
                        float h2[2];
                        #pragma unroll
                        for (int q = 0; q < 2; ++q) {
                            const int col = cb + 4 * (j + q);
                            float gi = smf[(OFF_B0P >> 2) + col]     + ft * smf[(OFF_WIH >> 2) + col];
                            float gf = smf[(OFF_B0P >> 2) + col + 1] + ft * smf[(OFF_WIH >> 2) + col + 1];
                            float gg = smf[(OFF_B0P >> 2) + col + 2] + ft * smf[(OFF_WIH >> 2) + col + 2];
                            float go = smf[(OFF_B0P >> 2) + col + 3] + ft * smf[(OFF_WIH >> 2) + col + 3];
                            if (hasg) {
                                gi += __uint_as_float(r[4 * (j + q)]);
                                gf += __uint_as_float(r[4 * (j + q) + 1]);
                                gg += __uint_as_float(r[4 * (j + q) + 2]);
                                go += __uint_as_float(r[4 * (j + q) + 3]);
                            }
                            float cn = siga(gf) * co[j + q] + siga(gi) * tanha(gg);
                            float hn = siga(go) * tanha(cn);
                            g_c0[(size_t)(u0 + j + q) * NS + grow] = cn;
                            h2[q] = hn;
                        }
                        oh[ch * 4 + (j >> 1)] = pack_hl(h2[0], h2[1], ol[ch * 4 + (j >> 1)]);
                    }
                }
                if (hasg) {
                    if (lo_half) { MBAR_WAIT(gdB, (u32)gphB); }
                    gphB ^= 1;
                }
                #pragma unroll
                for (int ch = 0; ch < 4; ++ch)
                    #pragma unroll
                    for (int jp = 0; jp < 4; ++jp) {
                        int u = 32 * cho + 8 * ch + 2 * jp;
                        u32 base = (u32)((u >> 6) * 16384) + swz((u32)(row_l * 128 + (u & 63) * 2));
                        *(u32*)(smem + A_H0HI + base) = oh[ch * 4 + jp];
                        *(u32*)(smem + A_H0LO + base) = ol[ch * 4 + jp];
                    }
                FENCE_ASYNC();
                __syncwarp();
                if (lane == 0) MBAR_ARRIVE(lo_half ? epL : epH);
            }
            // ---------- layer 1 epilogue (arrives tmL/tmH early) ----------
            {
                const bool last = (t == 5);
                if (lo_half) { MBAR_WAIT(gdA, (u32)gphA); }
                gphA ^= 1;
                if (!lo_half || last) { MBAR_WAIT(gdB, (u32)gphB); }
                T5_FENCE_A();
                u32 oh[16], ol[16];
                #pragma unroll
                for (int ch = 0; ch < 4; ++ch) {
                    const int cb = 128 * cho + 32 * ch;
                    const int u0 = 32 * cho + 8 * ch;
                    float co[8], hsv[8];
                    #pragma unroll
                    for (int jj = 0; jj < 8; ++jj) {
                        co[jj]  = (t > 0) ? g_c1[(size_t)(u0 + jj) * NS + grow] : 0.f;
                        hsv[jj] = (t > 0) ? g_hs[(size_t)(u0 + jj) * NS + grow] : 0.f;
                    }
                    u32 r[32];
                    LDTM32(r, tm_lane + (u32)cb); T5_WAIT_LD();
                    #pragma unroll
                    for (int j = 0; j < 8; j += 2) {
                        float h2[2], m2[2];
                        #pragma unroll
                        for (int q = 0; q < 2; ++q) {
                            const int col = cb + 4 * (j + q);
                            float gi = __uint_as_float(r[4 * (j + q)])     + smf[(OFF_B1P >> 2) + col];
                            float gf = __uint_as_float(r[4 * (j + q) + 1]) + smf[(OFF_B1P >> 2) + col + 1];
                            float gg = __uint_as_float(r[4 * (j + q) + 2]) + smf[(OFF_B1P >> 2) + col + 2];
                            float go = __uint_as_float(r[4 * (j + q) + 3]) + smf[(OFF_B1P >> 2) + col + 3];
                            float cn = siga(gf) * co[j + q] + siga(gi) * tanha(gg);
                            float hn = siga(go) * tanha(cn);
                            g_c1[(size_t)(u0 + j + q) * NS + grow] = cn;
                            float s = hsv[j + q] + hn;
                            if (!last) g_hs[(size_t)(u0 + j + q) * NS + grow] = s;
                            h2[q] = hn;
                            m2[q] = s * (1.f / 6.f);
                        }
                        const int jp = j >> 1;
                        oh[ch * 4 + jp] = pack_hl(h2[0], h2[1], ol[ch * 4 + jp]);
                        if (last) {
                            int u = u0 + j;
                            u32 base = (u32)((u >> 6) * 16384) + swz((u32)(row_l * 128 + (u & 63) * 2));
                            *(u32*)(smem + A_H1HI + base) = oh[ch * 4 + jp];
                            *(u32*)(smem + A_H1LO + base) = ol[ch * 4 + jp];
                            u32 mlo; u32 mhi = pack_hl(m2[0], m2[1], mlo);
                            *(u32*)(smem + A_H0HI + base) = mhi;   // mean = feat k[128,256)
                            *(u32*)(smem + A_H0LO + base) = mlo;
                        }
                    }
                }
                // Early TMEM-free signal: LDTMs for this half are complete.
                if (!last) {
                    T5_FENCE_B();
                    __syncwarp();
                    if (lane == 0) MBAR_ARRIVE(lo_half ? tmL : tmH);
                }
                if (!last) {
                    if (lo_half) { MBAR_WAIT(gdB, (u32)gphB); }
                    gphB ^= 1;
                    #pragma unroll
                    for (int ch = 0; ch < 4; ++ch)
                        #pragma unroll
                        for (int jp = 0; jp < 4; ++jp) {
                            int u = 32 * cho + 8 * ch + 2 * jp;
                            u32 base = (u32)((u >> 6) * 16384) + swz((u32)(row_l * 128 + (u & 63) * 2));
                            *(u32*)(smem + A_H1HI + base) = oh[ch * 4 + jp];
                            *(u32*)(smem + A_H1LO + base) = ol[ch * 4 + jp];
                        }
                    FENCE_ASYNC();
                    __syncwarp();
                    // no epL/epH arrival for t<5 (L0 GEMM no longer waits it)
                } else {
                    gphB ^= 1;
                    FENCE_ASYNC();
                    __syncwarp();
                    if (lane == 0) MBAR_ARRIVE(lo_half ? epL : epH);
                }
            }
        }
        // ---------- dense epilogues ----------
        for (int l = 0; l < 3; ++l) {
            MBAR_WAIT(gdB, (u32)gphB); gphB ^= 1;
            T5_FENCE_A();
            const bool fin = (l == 2);
            #pragma unroll
            for (int ch = 0; ch < 2; ++ch) {
                const int cb = 64 * cho + 32 * ch;
                u32 r[32];
                LDTM32(r, tm_lane + (u32)cb); T5_WAIT_LD();
                #pragma unroll
                for (int j = 0; j < 32; j += 2) {
                    int n = cb + j;
                    float a0 = tanha(__uint_as_float(r[j])     + smf[(OFF_BD >> 2) + l * 256 + n]);
                    float a1 = tanha(__uint_as_float(r[j + 1]) + smf[(OFF_BD >> 2) + l * 256 + n + 1]);
                    if (!fin) {
                        u32 base = (u32)((n >> 6) * 16384) + swz((u32)(row_l * 128 + (n & 63) * 2));
                        u32 lo; u32 hi = pack_hl(a0, a1, lo);
                        *(u32*)(smem + OFF_AREG + base) = hi;
                        *(u32*)(smem + OFF_AREG + 65536 + base) = lo;
                    } else {
                        int n2 = n ^ ((row_l & 7) << 2);   // fp32, bank-swizzled
                        *(float2*)(smf + (OFF_AREG >> 2) + row_l * 256 + n2) = make_float2(a0, a1);
                    }
                }
            }
            if (!fin) {
                FENCE_ASYNC();
                __syncwarp();
                if (lane == 0) MBAR_ARRIVE(lo_half ? epL : epH);
            }
        }
    }

    __syncthreads();

    // ---------- output head ----------
    if (tid < 512) {
        const int rh = tid >> 2, o = tid & 3;
        const float* wo = smf + (OFF_WO >> 2) + o * 256;
        const float* arow = smf + (OFF_AREG >> 2) + rh * 256;
        const int s = (rh & 7) << 2;
        float s0 = 0.f, s1 = 0.f, s2 = 0.f, s3 = 0.f;
        #pragma unroll 8
        for (int kb = 0; kb < 64; ++kb) {
            int k = kb * 4;
            float4 v = *(const float4*)(arow + (k ^ s));
            s0 += v.x * wo[k];
            s1 += v.y * wo[k + 1];
            s2 += v.z * wo[k + 2];
            s3 += v.w * wo[k + 3];
        }
        out[(size_t)(row0 + rh) * 4 + o] = ((s0 + s1) + (s2 + s3)) + smf[(OFF_BO >> 2) + o];
    }

    __syncthreads();
    if (wrp == 0) T5_DEALLOC(tmem, 512);
#endif  // HAS_TC
}

// ============== compact fallback (never taken when tcgen05 exists) =========
__global__ void fb_net(
    const float* __restrict__ x, const float* __restrict__ y,
    const float* __restrict__ Wih0, const float* __restrict__ Whh0, const float* __restrict__ b0,
    const float* __restrict__ Wih1, const float* __restrict__ Whh1, const float* __restrict__ b1,
    const float* __restrict__ Wd0, const float* __restrict__ bd0,
    const float* __restrict__ Wd1, const float* __restrict__ bd1,
    const float* __restrict__ Wd2, const float* __restrict__ bd2,
    const float* __restrict__ Wo,  const float* __restrict__ bo,
    float* __restrict__ out)
{
    if (g_use_tc) return;
    __shared__ float h0[128], c0[128], h1[128], c1[128], hs[128], feat[256], buf[2][256];
    const int u = threadIdx.x;
    for (int s = blockIdx.x; s < NS; s += gridDim.x) {
        float xn = 2.f * x[s] - 1.f, yn = 2.f * y[s] - 1.f;
        h0[u] = c0[u] = h1[u] = c1[u] = hs[u] = 0.f;
        __syncthreads();
        for (int t = 0; t < 6; ++t) {
            float ft = (t == 0) ? xn : (t == 1) ? yn : (t == 2) ? xn + yn
                     : (t == 3) ? xn - yn : (t == 4) ? xn * yn : xn * xn + yn * yn;
            float g[4];
            for (int gi = 0; gi < 4; ++gi) {
                int row = gi * 128 + u;
                float acc = b0[row] + Wih0[row] * ft;
                for (int k = 0; k < 128; ++k) acc += Whh0[row * 128 + k] * h0[k];
                g[gi] = acc;
            }
            float cn = sigf(g[1]) * c0[u] + sigf(g[0]) * tanhf_fast(g[2]);
            float hn = sigf(g[3]) * tanhf_fast(cn);
            __syncthreads();
            c0[u] = cn; h0[u] = hn;
            __syncthreads();
            for (int gi = 0; gi < 4; ++gi) {
                int row = gi * 128 + u;
                float acc = b1[row];
                for (int k = 0; k < 128; ++k)
                    acc += Wih1[row * 128 + k] * h0[k] + Whh1[row * 128 + k] * h1[k];
                g[gi] = acc;
            }
            cn = sigf(g[1]) * c1[u] + sigf(g[0]) * tanhf_fast(g[2]);
            hn = sigf(g[3]) * tanhf_fast(cn);
            __syncthreads();
            c1[u] = cn; h1[u] = hn; hs[u] += hn;
            __syncthreads();
        }
        feat[u] = h1[u]; feat[128 + u] = hs[u] * (1.f / 6.f);
        __syncthreads();
        const float* cur = feat;
        for (int l = 0; l < 3; ++l) {
            const float* W = (l == 0) ? Wd0 : (l == 1) ? Wd1 : Wd2;
            const float* bb = (l == 0) ? bd0 : (l == 1) ? bd1 : bd2;
            float* nxt = buf[l & 1];
            for (int n = u; n < 256; n += 128) {
                float acc = bb[n];
                for (int k = 0; k < 256; ++k) acc += W[n * 256 + k] * cur[k];
                nxt[n] = tanhf_fast(acc);
            }
            __syncthreads();
            cur = nxt;
        }
        if (u < 4) {
            float acc = bo[u];
            for (int k = 0; k < 256; ++k) acc += Wo[u * 256 + k] * cur[k];
            out[(size_t)s * 4 + u] = acc;
        }
        __syncthreads();
    }
}

// ======================= host launcher =====================================
extern "C" void kernel_launch(void* const* d_in, const int* in_sizes, int n_in,
                              void* d_out, int out_size)
{
    const float* x    = (const float*)d_in[0];
    const float* y    = (const float*)d_in[1];
    const float* Wih0 = (const float*)d_in[2];
    const float* Whh0 = (const float*)d_in[3];
    const float* b0   = (const float*)d_in[4];
    const float* Wih1 = (const float*)d_in[5];
    const float* Whh1 = (const float*)d_in[6];
    const float* b1   = (const float*)d_in[7];
    const float* Wd0  = (const float*)d_in[8];
    const float* bd0  = (const float*)d_in[9];
    const float* Wd1  = (const float*)d_in[10];
    const float* bd1  = (const float*)d_in[11];
    const float* Wd2  = (const float*)d_in[12];
    const float* bd2  = (const float*)d_in[13];
    const float* Wo   = (const float*)d_in[14];
    const float* bo   = (const float*)d_in[15];
    float* out = (float*)d_out;

    prep<<<384, 256>>>(Whh0, Wih1, Whh1, Wd0, Wd1, Wd2, Wih0, b0, b1);

    cudaFuncSetAttribute(fused_net, cudaFuncAttributeMaxDynamicSharedMemorySize, SMEM_BYTES);
    fused_net<<<NS / 128, 544, SMEM_BYTES>>>(x, y, bd0, bd1, bd2, Wo, bo, out);

    fb_net<<<512, 128>>>(x, y, Wih0, Whh0, b0, Wih1, Whh1, b1,
                         Wd0, bd0, Wd1, bd1, Wd2, bd2, Wo, bo, out);
}